// round 4
// baseline (speedup 1.0000x reference)
#include <cuda_runtime.h>
#include <math.h>

#define H 1536
#define HK 8
#define HV 16
#define DK 64
#define DV 64
#define KEY_DIM 512
#define VALUE_DIM 1024
#define CONV_DIM 2048
#define NROWS (CONV_DIM + VALUE_DIM + 2*HV)   // 3104
#define NB 388                                 // 388*8 = 3104 gemv_in rows
#define OUTB 384                               // 384*4 = 1536 gemv_out rows

__device__ float g_qkv[CONV_DIM];
__device__ float g_z[VALUE_DIM];
__device__ float g_ab[2*HV];
__device__ float g_outf[VALUE_DIM];
__device__ volatile int g_c1;   // gemv_in done counter
__device__ volatile int g_c2;   // delta done counter
__device__ int g_c3;            // exit counter (resets the others)

__device__ __forceinline__ float warp_sum(float v) {
#pragma unroll
    for (int o = 16; o > 0; o >>= 1) v += __shfl_xor_sync(0xffffffffu, v, o);
    return v;
}

__device__ __forceinline__ void cp16(void* s, const void* g) {
    unsigned sa = (unsigned)__cvta_generic_to_shared(s);
    asm volatile("cp.async.cg.shared.global [%0], [%1], 16;\n" :: "r"(sa), "l"(g));
}
__device__ __forceinline__ void cp_commit() { asm volatile("cp.async.commit_group;\n"); }
__device__ __forceinline__ void cp_wait1()  { asm volatile("cp.async.wait_group 1;\n" ::: "memory"); }
__device__ __forceinline__ void cp_wait0()  { asm volatile("cp.async.wait_group 0;\n" ::: "memory"); }

struct __align__(16) SM {
    float x[H];              // 6144B; x[0..1023] reused as o_final in out phase
    float wout[4*VALUE_DIM]; // 16KB: this block's 4 W_out rows
    float st[DK*DV];         // 16KB: this head's state (blocks 0..15)
    float qkv3[192];         // conv results: q[0:64) k[64:128) v[128:192)
    float red[512];          // reduction scratch
    float scal[8];           // qs, ks, qk, eg, beta, rms
};

__global__ __launch_bounds__(256, 4) void fused_kernel(
    const float* __restrict__ x,
    const float* __restrict__ Wqkv, const float* __restrict__ Wz,
    const float* __restrict__ Wa,   const float* __restrict__ Wb,
    const float* __restrict__ Wout,
    const float* __restrict__ convw, const float* __restrict__ Alog,
    const float* __restrict__ dtb,   const float* __restrict__ nw,
    const float* __restrict__ state, const float* __restrict__ cache,
    float* __restrict__ y)
{
    __shared__ SM sm;
    const int tid  = threadIdx.x;
    const int bid  = blockIdx.x;
    const int lane = tid & 31;
    const int wid  = tid >> 5;

    // ---- Phase 0: async prefetch. Group A = x; Group B = Wout slice (+state).
    for (int i = tid; i < H/4; i += 256) cp16(&sm.x[i*4], x + i*4);
    cp_commit();
    if (bid < OUTB) {
        const float* wsrc = Wout + (size_t)bid * 4 * VALUE_DIM;
        for (int i = tid; i < VALUE_DIM; i += 256) cp16(&sm.wout[i*4], wsrc + i*4);
    }
    if (bid < HV) {
        const float* ssrc = state + (size_t)bid * DK * DV;
        for (int i = tid; i < DK*DV/4; i += 256) cp16(&sm.st[i*4], ssrc + i*4);
    }
    cp_commit();
    cp_wait1();          // only group A (x) must be complete; B streams in background
    __syncthreads();

    // ---- Phase 1: fused input GEMVs (3104 rows, 1 warp/row, 8 rows/block)
    {
        const int row = bid * 8 + wid;
        const float* w; float* dst;
        if (row < CONV_DIM)                    { w = Wqkv + (size_t)row * H;                          dst = &g_qkv[row]; }
        else if (row < CONV_DIM + VALUE_DIM)   { int r = row - CONV_DIM;              w = Wz + (size_t)r * H; dst = &g_z[r]; }
        else if (row < CONV_DIM + VALUE_DIM + HV) { int r = row - CONV_DIM - VALUE_DIM; w = Wa + (size_t)r * H; dst = &g_ab[r]; }
        else                                   { int r = row - CONV_DIM - VALUE_DIM - HV; w = Wb + (size_t)r * H; dst = &g_ab[HV + r]; }

        const float4* w4 = (const float4*)w;
        const float4* s4 = (const float4*)sm.x;
        float acc0 = 0.f, acc1 = 0.f;
#pragma unroll
        for (int j = 0; j < H/128; j += 2) {
            float4 a0 = w4[lane + j*32],       b0 = s4[lane + j*32];
            float4 a1 = w4[lane + (j+1)*32],   b1 = s4[lane + (j+1)*32];
            acc0 += a0.x*b0.x + a0.y*b0.y + a0.z*b0.z + a0.w*b0.w;
            acc1 += a1.x*b1.x + a1.y*b1.y + a1.z*b1.z + a1.w*b1.w;
        }
        float acc = warp_sum(acc0 + acc1);
        if (lane == 0) __stcg(dst, acc);
    }
    __threadfence();
    __syncthreads();
    if (tid == 0) atomicAdd((int*)&g_c1, 1);

    // ---- Phase 2: delta rule (blocks 0..15, one per value head)
    if (bid < HV) {
        if (tid == 0) { while (g_c1 != NB) __nanosleep(64); }
        __syncthreads();
        __threadfence();
        cp_wait0();              // state now in smem
        __syncthreads();

        const int h = bid, kh = h >> 1;
        float* sq = &sm.qkv3[0];
        float* sk = &sm.qkv3[64];
        float* sv = &sm.qkv3[128];

        if (tid < 192) {
            int ch;
            if (tid < 64)       ch = kh * 64 + tid;
            else if (tid < 128) ch = KEY_DIM + kh * 64 + (tid - 64);
            else                ch = 2 * KEY_DIM + h * 64 + (tid - 128);
            float co = __ldcg(&g_qkv[ch]) * convw[ch*4 + 3]
                     + cache[ch*3 + 0]    * convw[ch*4 + 0]
                     + cache[ch*3 + 1]    * convw[ch*4 + 1]
                     + cache[ch*3 + 2]    * convw[ch*4 + 2];
            co = co / (1.f + expf(-co));             // silu
            sm.qkv3[tid] = co;
        }
        __syncthreads();

        if (wid == 0) {
            float a = sq[lane], b = sq[lane+32];
            float s = warp_sum(a*a + b*b);
            if (lane == 0) sm.scal[0] = rsqrtf(s + 1e-12f) * 0.125f;   // *Dk^-0.5
        } else if (wid == 1) {
            float a = sk[lane], b = sk[lane+32];
            float s = warp_sum(a*a + b*b);
            if (lane == 0) sm.scal[1] = rsqrtf(s + 1e-12f);
        } else if (wid == 2) {
            float s = warp_sum(sq[lane]*sk[lane] + sq[lane+32]*sk[lane+32]);
            if (lane == 0) sm.scal[2] = s;
        } else if (wid == 3 && lane == 0) {
            float aa = __ldcg(&g_ab[h]) + dtb[h];
            float sp = (aa > 20.f) ? aa : log1pf(expf(aa));            // softplus
            sm.scal[3] = expf(-expf(Alog[h]) * sp);                    // exp(g)
            sm.scal[4] = 1.f / (1.f + expf(-__ldcg(&g_ab[HV + h])));   // beta
        }
        __syncthreads();

        const float qk = sm.scal[2] * sm.scal[0] * sm.scal[1];
        const float eg = sm.scal[3], beta = sm.scal[4];
        if (tid < 64)       sq[tid]      *= sm.scal[0];
        else if (tid < 128) sk[tid - 64] *= sm.scal[1];
        __syncthreads();

        // S^T q and S^T k: 4 k-quarters per v column
        const int v  = tid & 63;
        const int kq = tid >> 6;
        float ar = 0.f, ao = 0.f;
#pragma unroll
        for (int kk = 0; kk < 16; ++kk) {
            int k = kq * 16 + kk;
            float s = sm.st[k * DV + v];
            ar += s * sk[k];
            ao += s * sq[k];
        }
        sm.red[tid] = ar; sm.red[256 + tid] = ao;
        __syncthreads();

        if (tid < 64) {
            float r0 = sm.red[v] + sm.red[64+v] + sm.red[128+v] + sm.red[192+v];
            float o0 = sm.red[256+v] + sm.red[320+v] + sm.red[384+v] + sm.red[448+v];
            float delta = (sv[v] - eg * r0) * beta;
            float out   = eg * o0 + qk * delta;
            sm.red[v] = out * out;
            sm.red[256 + v] = out;
        }
        __syncthreads();
        if (wid == 0) {
            float s = warp_sum(sm.red[lane] + sm.red[lane + 32]);
            if (lane == 0) sm.scal[5] = rsqrtf(s * (1.f/64.f) + 1e-6f);
        }
        __syncthreads();
        if (tid < 64) {
            float zg  = __ldcg(&g_z[h*64 + v]);
            float sil = zg / (1.f + expf(-zg));
            __stcg(&g_outf[h*64 + v], nw[v] * sm.red[256 + v] * sm.scal[5] * sil);
        }
        __threadfence();
        __syncthreads();
        if (tid == 0) atomicAdd((int*)&g_c2, 1);
    }

    // ---- Phase 3: y = W_out @ out_final (from smem-prefetched W_out)
    if (tid == 0) { while (g_c2 != HV) __nanosleep(64); }
    __syncthreads();
    __threadfence();
    if (bid < OUTB) {
        cp_wait0();                    // Wout slice resident in smem
        for (int i = tid; i < VALUE_DIM; i += 256)
            sm.x[i] = __ldcg(&g_outf[i]);   // reuse x region as o_final
        __syncthreads();

        // 8 warps, 2 warps per row (512 elements each)
        const int r = wid >> 1, half = wid & 1;
        const float* wr = &sm.wout[r * VALUE_DIM + half * 512];
        const float* ov = &sm.x[half * 512];
        float a = 0.f;
#pragma unroll
        for (int j = 0; j < 16; ++j)
            a += wr[lane + j*32] * ov[lane + j*32];
        a = warp_sum(a);
        if (lane == 0) sm.red[wid] = a;
        __syncthreads();
        if (tid < 4) y[bid*4 + tid] = sm.red[2*tid] + sm.red[2*tid + 1];
    }

    // ---- Exit: last block resets counters for next (graph-replayed) launch
    if (tid == 0) {
        int t = atomicAdd(&g_c3, 1);
        if (t == NB - 1) { g_c3 = 0; g_c1 = 0; g_c2 = 0; }
    }
}

extern "C" void kernel_launch(void* const* d_in, const int* in_sizes, int n_in,
                              void* d_out, int out_size)
{
    const float* x     = (const float*)d_in[0];
    const float* Wqkv  = (const float*)d_in[1];
    const float* Wz    = (const float*)d_in[2];
    const float* Wa    = (const float*)d_in[3];
    const float* Wb    = (const float*)d_in[4];
    const float* Wout  = (const float*)d_in[5];
    const float* convw = (const float*)d_in[6];
    const float* Alog  = (const float*)d_in[7];
    const float* dtb   = (const float*)d_in[8];
    const float* nw    = (const float*)d_in[9];
    const float* state = (const float*)d_in[10];
    const float* cache = (const float*)d_in[11];
    float* y = (float*)d_out;

    fused_kernel<<<NB, 256>>>(x, Wqkv, Wz, Wa, Wb, Wout, convw, Alog, dtb, nw,
                              state, cache, y);
}

// round 5
// speedup vs baseline: 1.4800x; 1.4800x over previous
#include <cuda_runtime.h>
#include <math.h>

#define H 1536
#define HK 8
#define HV 16
#define DK 64
#define DV 64
#define KEY_DIM 512
#define VALUE_DIM 1024
#define CONV_DIM 2048
#define NROWS (CONV_DIM + VALUE_DIM + 2*HV)   // 3104

__device__ __align__(16) float g_qkv[CONV_DIM];
__device__ __align__(16) float g_z[VALUE_DIM];
__device__ __align__(16) float g_ab[2*HV];
__device__ __align__(16) float g_outf[VALUE_DIM];

__device__ __forceinline__ float warp_sum(float v) {
#pragma unroll
    for (int o = 16; o > 0; o >>= 1) v += __shfl_xor_sync(0xffffffffu, v, o);
    return v;
}

// ---------------- Kernel A: fused input GEMVs (qkv, z, a, b) -----------------
// 3104 rows x 1536 cols. TWO warps per row (768 cols each), 4 rows per block.
// 776 blocks -> 6208 warps resident; 6 front-batched float4 loads per warp.
__global__ __launch_bounds__(256) void gemv_in(
    const float* __restrict__ x,
    const float* __restrict__ Wqkv, const float* __restrict__ Wz,
    const float* __restrict__ Wa,   const float* __restrict__ Wb)
{
    __shared__ __align__(16) float sx[H];
    __shared__ float part[8];
    const int tid = threadIdx.x;
#pragma unroll
    for (int i = tid; i < H / 4; i += 256)
        ((float4*)sx)[i] = ((const float4*)x)[i];
    __syncthreads();

    const int lane = tid & 31;
    const int wid  = tid >> 5;
    const int row  = blockIdx.x * 4 + (wid >> 1);
    const int half = wid & 1;

    const float* w;
    if (row < CONV_DIM)                         w = Wqkv + (size_t)row * H;
    else if (row < CONV_DIM + VALUE_DIM)        w = Wz + (size_t)(row - CONV_DIM) * H;
    else if (row < CONV_DIM + VALUE_DIM + HV)   w = Wa + (size_t)(row - CONV_DIM - VALUE_DIM) * H;
    else                                        w = Wb + (size_t)(row - CONV_DIM - VALUE_DIM - HV) * H;

    // this warp's 768-float half: 192 float4, 6 iterations of 32
    const float4* w4 = (const float4*)w + half * 192 + lane;
    const float4* s4 = (const float4*)sx + half * 192 + lane;

    float4 a0 = w4[0],  a1 = w4[32], a2 = w4[64],
           a3 = w4[96], a4 = w4[128], a5 = w4[160];   // front-batched global loads
    float4 b0 = s4[0],  b1 = s4[32], b2 = s4[64],
           b3 = s4[96], b4 = s4[128], b5 = s4[160];

    float acc = a0.x*b0.x + a0.y*b0.y + a0.z*b0.z + a0.w*b0.w;
    acc += a1.x*b1.x + a1.y*b1.y + a1.z*b1.z + a1.w*b1.w;
    acc += a2.x*b2.x + a2.y*b2.y + a2.z*b2.z + a2.w*b2.w;
    acc += a3.x*b3.x + a3.y*b3.y + a3.z*b3.z + a3.w*b3.w;
    acc += a4.x*b4.x + a4.y*b4.y + a4.z*b4.z + a4.w*b4.w;
    acc += a5.x*b5.x + a5.y*b5.y + a5.z*b5.z + a5.w*b5.w;

    acc = warp_sum(acc);
    if (lane == 0) part[wid] = acc;
    __syncthreads();

    if (tid < 4) {
        const int r = blockIdx.x * 4 + tid;
        float v = part[2*tid] + part[2*tid + 1];
        float* dst;
        if (r < CONV_DIM)                        dst = &g_qkv[r];
        else if (r < CONV_DIM + VALUE_DIM)       dst = &g_z[r - CONV_DIM];
        else if (r < CONV_DIM + VALUE_DIM + HV)  dst = &g_ab[r - CONV_DIM - VALUE_DIM];
        else                                     dst = &g_ab[HV + r - CONV_DIM - VALUE_DIM - HV];
        *dst = v;
    }
}

// ------------- Kernel B: conv + l2norm + delta rule + gated RMSNorm ----------
__global__ __launch_bounds__(256) void delta_kernel(
    const float* __restrict__ convw, const float* __restrict__ Alog,
    const float* __restrict__ dtb,   const float* __restrict__ nw,
    const float* __restrict__ state, const float* __restrict__ cache)
{
    const int h   = blockIdx.x;       // value head 0..15
    const int kh  = h >> 1;           // key head (repeat factor 2)
    const int tid = threadIdx.x;
    const int lane = tid & 31, wid = tid >> 5;

    __shared__ float sq[DK], sk[DK], sv[DV];
    __shared__ float s_qs, s_ks, s_qk, s_eg, s_beta, s_rms;
    __shared__ float r_part[256], o_part[256];

    if (tid < 192) {
        int ch;
        if (tid < 64)       ch = kh * 64 + tid;
        else if (tid < 128) ch = KEY_DIM + kh * 64 + (tid - 64);
        else                ch = 2 * KEY_DIM + h * 64 + (tid - 128);
        float co = g_qkv[ch]         * convw[ch * 4 + 3]
                 + cache[ch * 3 + 0] * convw[ch * 4 + 0]
                 + cache[ch * 3 + 1] * convw[ch * 4 + 1]
                 + cache[ch * 3 + 2] * convw[ch * 4 + 2];
        co = co / (1.f + expf(-co));  // silu
        if (tid < 64)       sq[tid] = co;
        else if (tid < 128) sk[tid - 64] = co;
        else                sv[tid - 128] = co;
    }
    __syncthreads();

    if (wid == 0) {
        float a = sq[lane], b = sq[lane + 32];
        float s = warp_sum(a * a + b * b);
        if (lane == 0) s_qs = rsqrtf(s + 1e-12f) * 0.125f;  // * Dk^-0.5
    } else if (wid == 1) {
        float a = sk[lane], b = sk[lane + 32];
        float s = warp_sum(a * a + b * b);
        if (lane == 0) s_ks = rsqrtf(s + 1e-12f);
    } else if (wid == 2) {
        float s = warp_sum(sq[lane] * sk[lane] + sq[lane + 32] * sk[lane + 32]);
        if (lane == 0) s_qk = s;
    } else if (wid == 3 && lane == 0) {
        float aa = g_ab[h] + dtb[h];
        float sp = (aa > 20.f) ? aa : log1pf(expf(aa));      // softplus
        s_eg = expf(-expf(Alog[h]) * sp);                    // exp(g)
        s_beta = 1.f / (1.f + expf(-g_ab[HV + h]));          // sigmoid
    }
    __syncthreads();

    const float qk = s_qk * s_qs * s_ks;

    if (tid < 64)       sq[tid]      *= s_qs;
    else if (tid < 128) sk[tid - 64] *= s_ks;
    __syncthreads();

    const int v  = tid & 63;
    const int kq = tid >> 6;
    const float* st = state + (size_t)h * DK * DV;
    float ar = 0.f, ao = 0.f;
#pragma unroll
    for (int kk = 0; kk < 16; ++kk) {
        int k = kq * 16 + kk;
        float s = st[k * DV + v];
        ar += s * sk[k];
        ao += s * sq[k];
    }
    r_part[tid] = ar; o_part[tid] = ao;
    __syncthreads();

    if (tid < 64) {
        float r0 = r_part[v] + r_part[64 + v] + r_part[128 + v] + r_part[192 + v];
        float o0 = o_part[v] + o_part[64 + v] + o_part[128 + v] + o_part[192 + v];
        float delta = (sv[v] - s_eg * r0) * s_beta;
        float out   = s_eg * o0 + qk * delta;
        r_part[v] = out * out;
        o_part[v] = out;
    }
    __syncthreads();
    if (wid == 0) {
        float s = warp_sum(r_part[lane] + r_part[lane + 32]);
        if (lane == 0) s_rms = rsqrtf(s * (1.f / 64.f) + 1e-6f);
    }
    __syncthreads();
    if (tid < 64) {
        float zg  = g_z[h * 64 + v];
        float sil = zg / (1.f + expf(-zg));
        g_outf[h * 64 + v] = nw[v] * o_part[v] * s_rms * sil;
    }
}

// ---------------- Kernel C: y = W_out @ out_final ----------------------------
// 1536 rows x 1024 cols. TWO warps per row (512 cols each), 4 rows per block.
__global__ __launch_bounds__(256) void gemv_out(
    const float* __restrict__ Wout, float* __restrict__ y)
{
    __shared__ __align__(16) float so[VALUE_DIM];
    __shared__ float part[8];
    const int tid = threadIdx.x;
#pragma unroll
    for (int i = tid; i < VALUE_DIM / 4; i += 256)
        ((float4*)so)[i] = ((const float4*)g_outf)[i];
    __syncthreads();

    const int lane = tid & 31;
    const int wid  = tid >> 5;
    const int row  = blockIdx.x * 4 + (wid >> 1);
    const int half = wid & 1;

    // 512 floats per half = 128 float4, 4 iterations of 32
    const float4* w4 = (const float4*)(Wout + (size_t)row * VALUE_DIM) + half * 128 + lane;
    const float4* s4 = (const float4*)so + half * 128 + lane;

    float4 a0 = w4[0], a1 = w4[32], a2 = w4[64], a3 = w4[96];
    float4 b0 = s4[0], b1 = s4[32], b2 = s4[64], b3 = s4[96];

    float acc = a0.x*b0.x + a0.y*b0.y + a0.z*b0.z + a0.w*b0.w;
    acc += a1.x*b1.x + a1.y*b1.y + a1.z*b1.z + a1.w*b1.w;
    acc += a2.x*b2.x + a2.y*b2.y + a2.z*b2.z + a2.w*b2.w;
    acc += a3.x*b3.x + a3.y*b3.y + a3.z*b3.z + a3.w*b3.w;

    acc = warp_sum(acc);
    if (lane == 0) part[wid] = acc;
    __syncthreads();
    if (tid < 4) y[blockIdx.x * 4 + tid] = part[2*tid] + part[2*tid + 1];
}

extern "C" void kernel_launch(void* const* d_in, const int* in_sizes, int n_in,
                              void* d_out, int out_size)
{
    const float* x     = (const float*)d_in[0];
    const float* Wqkv  = (const float*)d_in[1];
    const float* Wz    = (const float*)d_in[2];
    const float* Wa    = (const float*)d_in[3];
    const float* Wb    = (const float*)d_in[4];
    const float* Wout  = (const float*)d_in[5];
    const float* convw = (const float*)d_in[6];
    const float* Alog  = (const float*)d_in[7];
    const float* dtb   = (const float*)d_in[8];
    const float* nw    = (const float*)d_in[9];
    const float* state = (const float*)d_in[10];
    const float* cache = (const float*)d_in[11];
    float* y = (float*)d_out;

    gemv_in<<<NROWS / 4, 256>>>(x, Wqkv, Wz, Wa, Wb);
    delta_kernel<<<HV, 256>>>(convw, Alog, dtb, nw, state, cache);
    gemv_out<<<H / 4, 256>>>(Wout, y);
}